// round 2
// baseline (speedup 1.0000x reference)
#include <cuda_runtime.h>
#include <mma.h>

using namespace nvcuda;

#define FDIM     128
#define TM       32          // nodes per CTA
#define VLD      132         // smem leading dim (floats), mult of 4
#define NTHREADS 256

// Pre-converted (tf32-rounded) weights, filled by prep_kernel each launch.
__device__ float g_wcat[128 * 256];   // [k][0:128]=U_w, [k][128:256]=V_w
__device__ float g_m1[256 * 128];
__device__ float g_m2[128 * 384];

__device__ __forceinline__ float ftf32(float x) {
    float y;
    asm("cvt.rna.tf32.f32 %0, %1;" : "=f"(y) : "f"(x));
    return y;
}

__global__ void prep_kernel(const float* __restrict__ Uw,
                            const float* __restrict__ Vw,
                            const float* __restrict__ m1w,
                            const float* __restrict__ m2w) {
    int i = blockIdx.x * blockDim.x + threadIdx.x;
    if (i < 128 * 128) {
        int k = i >> 7, g = i & 127;
        g_wcat[k * 256 + g]       = ftf32(Uw[i]);
        g_wcat[k * 256 + 128 + g] = ftf32(Vw[i]);
    }
    if (i < 256 * 128) g_m1[i] = ftf32(m1w[i]);
    if (i < 128 * 384) g_m2[i] = ftf32(m2w[i]);
}

using FragA = wmma::fragment<wmma::matrix_a, 16, 16, 8, wmma::precision::tf32, wmma::row_major>;
using FragB = wmma::fragment<wmma::matrix_b, 16, 16, 8, wmma::precision::tf32, wmma::row_major>;
using FragC = wmma::fragment<wmma::accumulator, 16, 16, 8, float>;

__global__ __launch_bounds__(NTHREADS, 1)
void painn_kernel(const float* __restrict__ node_feat,
                  const float* __restrict__ U_b,
                  const float* __restrict__ V_b,
                  const float* __restrict__ m1_b,
                  const float* __restrict__ m2_b,
                  float* __restrict__ out) {
    extern __shared__ float smem[];
    // Layout (floats):
    float* sVec   = smem;                 // 96 x VLD : vec rows r=n*3+c (tf32-rounded)
    float* sUv    = sVec   + 96 * VLD;    // 96 x VLD
    float* sVv    = sUv    + 96 * VLD;    // 96 x VLD, reused later as sOut[3][32][VLD]
    float* sScal  = sVv    + 96 * VLD;    // 32 x VLD (tf32-rounded scalars)
    float* sVn    = sScal  + 32 * VLD;    // 32 x VLD
    float* sInner = sVn    + 32 * VLD;    // 32 x VLD (fp32)
    float* sH     = sInner + 32 * VLD;    // 32 x VLD

    const int tid = threadIdx.x;
    const int w   = tid >> 5;
    const int base = blockIdx.x * (TM * 4 * FDIM);   // floats
    const float* nf = node_feat + base;

    // ---------- Stage 0: stage node tile into smem (tf32-rounded) ----------
    for (int q = tid; q < TM * 128; q += NTHREADS) {   // TM*512/4 float4s
        int n   = q >> 7;
        int f0  = (q & 127) * 4;
        float4 v = *reinterpret_cast<const float4*>(nf + n * 512 + f0);
        float r0 = ftf32(v.x), r1 = ftf32(v.y), r2 = ftf32(v.z), r3 = ftf32(v.w);
        float* dst;
        if (f0 < 128) {
            dst = sScal + n * VLD + f0;
        } else {
            int c = (f0 - 128) >> 7;
            int f = (f0 - 128) & 127;
            dst = sVec + (n * 3 + c) * VLD + f;
        }
        dst[0] = r0; dst[1] = r1; dst[2] = r2; dst[3] = r3;
    }
    __syncthreads();

    // ---------- Stage 1: G1 = vec(96x128) @ [U|V](128x256) ----------
    {
        FragB bf[16];
        #pragma unroll
        for (int nti = 0; nti < 2; ++nti) {
            int nt = w + nti * 8;                 // 0..15 column tile
            const float* bbase = g_wcat + nt * 16;
            #pragma unroll
            for (int k0 = 0; k0 < 16; ++k0)
                wmma::load_matrix_sync(bf[k0], bbase + k0 * 8 * 256, 256);
            for (int mt = 0; mt < 6; ++mt) {
                FragC acc;
                wmma::fill_fragment(acc, 0.0f);
                #pragma unroll
                for (int k0 = 0; k0 < 16; ++k0) {
                    FragA af;
                    wmma::load_matrix_sync(af, sVec + mt * 16 * VLD + k0 * 8, VLD);
                    wmma::mma_sync(acc, af, bf[k0], acc);
                }
                float* dst = (nt < 8 ? sUv + nt * 16 : sVv + (nt - 8) * 16) + mt * 16 * VLD;
                wmma::store_matrix_sync(dst, acc, VLD, wmma::mem_row_major);
            }
        }
    }
    __syncthreads();

    // ---------- Stage 2: bias, Vv_norm, inner product ----------
    for (int q = tid; q < TM * 128; q += NTHREADS) {
        int n = q >> 7, g = q & 127;
        float ub = U_b[g], vb = V_b[g];
        int r = 3 * n;
        float u0 = sUv[(r + 0) * VLD + g] + ub;
        float u1 = sUv[(r + 1) * VLD + g] + ub;
        float u2 = sUv[(r + 2) * VLD + g] + ub;
        float v0 = sVv[(r + 0) * VLD + g] + vb;
        float v1 = sVv[(r + 1) * VLD + g] + vb;
        float v2 = sVv[(r + 2) * VLD + g] + vb;
        sUv[(r + 0) * VLD + g] = u0;   // keep biased Uv for epilogue
        sUv[(r + 1) * VLD + g] = u1;
        sUv[(r + 2) * VLD + g] = u2;
        sVn[n * VLD + g]    = ftf32(sqrtf(v0 * v0 + v1 * v1 + v2 * v2));
        sInner[n * VLD + g] = u0 * v0 + u1 * v1 + u2 * v2;
    }
    __syncthreads();     // Vv dead -> its space becomes sOut

    // ---------- Stage 3: G2 = [Vn | scal](32x256) @ m1(256x128) ----------
    {
        for (int mt = 0; mt < 2; ++mt) {
            FragC acc;
            wmma::fill_fragment(acc, 0.0f);
            #pragma unroll
            for (int k0 = 0; k0 < 16; ++k0) {
                FragA af; FragB bf2;
                wmma::load_matrix_sync(af, sVn + mt * 16 * VLD + k0 * 8, VLD);
                wmma::load_matrix_sync(bf2, g_m1 + k0 * 8 * 128 + w * 16, 128);
                wmma::mma_sync(acc, af, bf2, acc);
            }
            #pragma unroll
            for (int k0 = 0; k0 < 16; ++k0) {
                FragA af; FragB bf2;
                wmma::load_matrix_sync(af, sScal + mt * 16 * VLD + k0 * 8, VLD);
                wmma::load_matrix_sync(bf2, g_m1 + (128 + k0 * 8) * 128 + w * 16, 128);
                wmma::mma_sync(acc, af, bf2, acc);
            }
            wmma::store_matrix_sync(sH + mt * 16 * VLD + w * 16, acc, VLD, wmma::mem_row_major);
        }
    }
    __syncthreads();

    // silu + round
    for (int q = tid; q < TM * 128; q += NTHREADS) {
        int n = q >> 7, g = q & 127;
        float x = sH[n * VLD + g] + m1_b[g];
        float s = x / (1.0f + expf(-x));
        sH[n * VLD + g] = ftf32(s);
    }
    __syncthreads();

    // ---------- Stage 4: G3 = h(32x128) @ m2(128x384) ----------
    float* sOut = sVv;   // [3][32][VLD]: a_vv, a_sv, a_ss
    {
        FragB bf[16];
        #pragma unroll
        for (int nti = 0; nti < 3; ++nti) {
            int nt = w + nti * 8;                 // 0..23
            #pragma unroll
            for (int k0 = 0; k0 < 16; ++k0)
                wmma::load_matrix_sync(bf[k0], g_m2 + k0 * 8 * 384 + nt * 16, 384);
            for (int mt = 0; mt < 2; ++mt) {
                FragC acc;
                wmma::fill_fragment(acc, 0.0f);
                #pragma unroll
                for (int k0 = 0; k0 < 16; ++k0) {
                    FragA af;
                    wmma::load_matrix_sync(af, sH + mt * 16 * VLD + k0 * 8, VLD);
                    wmma::mma_sync(acc, af, bf[k0], acc);
                }
                int blk  = nt >> 3;
                int colc = (nt & 7) * 16;
                wmma::store_matrix_sync(sOut + blk * 32 * VLD + mt * 16 * VLD + colc,
                                        acc, VLD, wmma::mem_row_major);
            }
        }
    }
    __syncthreads();

    // ---------- Stage 5: epilogue (fp32 residual path, vectorized) ----------
    for (int q = tid; q < TM * 32; q += NTHREADS) {   // 1024 quads
        int n = q >> 5;
        int g = (q & 31) * 4;
        float4 avv = *reinterpret_cast<float4*>(sOut + 0 * 32 * VLD + n * VLD + g);
        float4 asv = *reinterpret_cast<float4*>(sOut + 1 * 32 * VLD + n * VLD + g);
        float4 ass = *reinterpret_cast<float4*>(sOut + 2 * 32 * VLD + n * VLD + g);
        float4 b0 = *reinterpret_cast<const float4*>(m2_b + g);
        float4 b1 = *reinterpret_cast<const float4*>(m2_b + 128 + g);
        float4 b2 = *reinterpret_cast<const float4*>(m2_b + 256 + g);
        avv.x += b0.x; avv.y += b0.y; avv.z += b0.z; avv.w += b0.w;
        asv.x += b1.x; asv.y += b1.y; asv.z += b1.z; asv.w += b1.w;
        ass.x += b2.x; ass.y += b2.y; ass.z += b2.z; ass.w += b2.w;
        float4 inn = *reinterpret_cast<float4*>(sInner + n * VLD + g);

        const float* nfr = node_feat + base + n * 512;
        float* outr = out + base + n * 512;

        float4 s = *reinterpret_cast<const float4*>(nfr + g);
        float4 os;
        os.x = s.x + asv.x * inn.x + ass.x;
        os.y = s.y + asv.y * inn.y + ass.y;
        os.z = s.z + asv.z * inn.z + ass.z;
        os.w = s.w + asv.w * inn.w + ass.w;
        *reinterpret_cast<float4*>(outr + g) = os;

        #pragma unroll
        for (int c = 0; c < 3; ++c) {
            float4 u = *reinterpret_cast<float4*>(sUv + (3 * n + c) * VLD + g);
            float4 v = *reinterpret_cast<const float4*>(nfr + 128 + c * 128 + g);
            float4 ov;
            ov.x = v.x + avv.x * u.x;
            ov.y = v.y + avv.y * u.y;
            ov.z = v.z + avv.z * u.z;
            ov.w = v.w + avv.w * u.w;
            *reinterpret_cast<float4*>(outr + 128 + c * 128 + g) = ov;
        }
    }
}

extern "C" void kernel_launch(void* const* d_in, const int* in_sizes, int n_in,
                              void* d_out, int out_size) {
    const float* node_feat = (const float*)d_in[0];
    const float* U_w  = (const float*)d_in[1];
    const float* U_b  = (const float*)d_in[2];
    const float* V_w  = (const float*)d_in[3];
    const float* V_b  = (const float*)d_in[4];
    const float* m1_w = (const float*)d_in[5];
    const float* m1_b = (const float*)d_in[6];
    const float* m2_w = (const float*)d_in[7];
    const float* m2_b = (const float*)d_in[8];
    float* out = (float*)d_out;

    int N = in_sizes[0] / (4 * FDIM);

    prep_kernel<<<(128 * 384 + 255) / 256, 256>>>(U_w, V_w, m1_w, m2_w);

    size_t smem_bytes = (size_t)(3 * 96 * VLD + 4 * 32 * VLD) * sizeof(float);
    cudaFuncSetAttribute(painn_kernel,
                         cudaFuncAttributeMaxDynamicSharedMemorySize,
                         (int)smem_bytes);
    painn_kernel<<<N / TM, NTHREADS, smem_bytes>>>(node_feat, U_b, V_b, m1_b, m2_b, out);
}

// round 3
// speedup vs baseline: 1.2439x; 1.2439x over previous
#include <cuda_runtime.h>
#include <mma.h>

using namespace nvcuda;

#define FDIM     128
#define TM       32          // nodes per CTA
#define VLD      132         // smem leading dim (floats), mult of 4
#define NTHREADS 512         // 16 warps

// Pre-converted (tf32-rounded) weights, filled by prep_kernel each launch.
__device__ float g_wcat[128 * 256];   // [k][0:128]=U_w, [k][128:256]=V_w
__device__ float g_m1[256 * 128];
__device__ float g_m2[128 * 384];

__device__ __forceinline__ float ftf32(float x) {
    float y;
    asm("cvt.rna.tf32.f32 %0, %1;" : "=f"(y) : "f"(x));
    return y;
}

__global__ void prep_kernel(const float* __restrict__ Uw,
                            const float* __restrict__ Vw,
                            const float* __restrict__ m1w,
                            const float* __restrict__ m2w) {
    int i = blockIdx.x * blockDim.x + threadIdx.x;
    if (i < 128 * 128) {
        int k = i >> 7, g = i & 127;
        g_wcat[k * 256 + g]       = ftf32(Uw[i]);
        g_wcat[k * 256 + 128 + g] = ftf32(Vw[i]);
    }
    if (i < 256 * 128) g_m1[i] = ftf32(m1w[i]);
    if (i < 128 * 384) g_m2[i] = ftf32(m2w[i]);
}

using FragA = wmma::fragment<wmma::matrix_a, 16, 16, 8, wmma::precision::tf32, wmma::row_major>;
using FragB = wmma::fragment<wmma::matrix_b, 16, 16, 8, wmma::precision::tf32, wmma::row_major>;
using FragC = wmma::fragment<wmma::accumulator, 16, 16, 8, float>;

__global__ __launch_bounds__(NTHREADS, 1)
void painn_kernel(const float* __restrict__ node_feat,
                  const float* __restrict__ U_b,
                  const float* __restrict__ V_b,
                  const float* __restrict__ m1_b,
                  const float* __restrict__ m2_b,
                  float* __restrict__ out) {
    extern __shared__ float smem[];
    float* sVec   = smem;                 // 96 x VLD : vec rows r=n*3+c (tf32-rounded)
    float* sUv    = sVec   + 96 * VLD;    // 96 x VLD
    float* sVv    = sUv    + 96 * VLD;    // 96 x VLD, reused later as sOut[3][32][VLD]
    float* sScal  = sVv    + 96 * VLD;    // 32 x VLD (tf32-rounded scalars)
    float* sVn    = sScal  + 32 * VLD;    // 32 x VLD
    float* sInner = sVn    + 32 * VLD;    // 32 x VLD (fp32)
    float* sH     = sInner + 32 * VLD;    // 32 x VLD

    const int tid = threadIdx.x;
    const int w   = tid >> 5;             // 0..15
    const int base = blockIdx.x * (TM * 4 * FDIM);
    const float* nf = node_feat + base;

    // ---------- Stage 0: stage node tile into smem (tf32-rounded) ----------
    for (int q = tid; q < TM * 128; q += NTHREADS) {
        int n   = q >> 7;
        int f0  = (q & 127) * 4;
        float4 v = *reinterpret_cast<const float4*>(nf + n * 512 + f0);
        float r0 = ftf32(v.x), r1 = ftf32(v.y), r2 = ftf32(v.z), r3 = ftf32(v.w);
        float* dst;
        if (f0 < 128) {
            dst = sScal + n * VLD + f0;
        } else {
            int c = (f0 - 128) >> 7;
            int f = (f0 - 128) & 127;
            dst = sVec + (n * 3 + c) * VLD + f;
        }
        dst[0] = r0; dst[1] = r1; dst[2] = r2; dst[3] = r3;
    }
    __syncthreads();

    // ---------- Stage 1: G1 = vec(96x128) @ [U|V](128x256) ----------
    // One 16-col output tile per warp (16 warps -> 16 tiles).
    {
        const int nt = w;
        FragB bf[16];
        const float* bbase = g_wcat + nt * 16;
        #pragma unroll
        for (int k0 = 0; k0 < 16; ++k0)
            wmma::load_matrix_sync(bf[k0], bbase + k0 * 8 * 256, 256);
        float* dcol = (nt < 8 ? sUv + nt * 16 : sVv + (nt - 8) * 16);
        for (int mt = 0; mt < 6; ++mt) {
            FragC acc;
            wmma::fill_fragment(acc, 0.0f);
            #pragma unroll
            for (int k0 = 0; k0 < 16; ++k0) {
                FragA af;
                wmma::load_matrix_sync(af, sVec + mt * 16 * VLD + k0 * 8, VLD);
                wmma::mma_sync(acc, af, bf[k0], acc);
            }
            wmma::store_matrix_sync(dcol + mt * 16 * VLD, acc, VLD, wmma::mem_row_major);
        }
    }
    __syncthreads();

    // ---------- Stage 2: bias, Vv_norm, inner product ----------
    for (int q = tid; q < TM * 128; q += NTHREADS) {
        int n = q >> 7, g = q & 127;
        float ub = U_b[g], vb = V_b[g];
        int r = 3 * n;
        float u0 = sUv[(r + 0) * VLD + g] + ub;
        float u1 = sUv[(r + 1) * VLD + g] + ub;
        float u2 = sUv[(r + 2) * VLD + g] + ub;
        float v0 = sVv[(r + 0) * VLD + g] + vb;
        float v1 = sVv[(r + 1) * VLD + g] + vb;
        float v2 = sVv[(r + 2) * VLD + g] + vb;
        sUv[(r + 0) * VLD + g] = u0;   // keep biased Uv for epilogue
        sUv[(r + 1) * VLD + g] = u1;
        sUv[(r + 2) * VLD + g] = u2;
        sVn[n * VLD + g]    = ftf32(sqrtf(v0 * v0 + v1 * v1 + v2 * v2));
        sInner[n * VLD + g] = u0 * v0 + u1 * v1 + u2 * v2;
    }
    __syncthreads();     // Vv dead -> its space becomes sOut

    // ---------- Stage 3: G2 = [Vn | scal](32x256) @ m1(256x128) ----------
    // 16 tasks: mt = w&1, nt = w>>1  (2 m-tiles x 8 n-tiles)
    {
        const int mt = w & 1;
        const int nt = w >> 1;
        FragC acc;
        wmma::fill_fragment(acc, 0.0f);
        #pragma unroll
        for (int k0 = 0; k0 < 16; ++k0) {
            FragA af; FragB bf2;
            wmma::load_matrix_sync(af, sVn + mt * 16 * VLD + k0 * 8, VLD);
            wmma::load_matrix_sync(bf2, g_m1 + k0 * 8 * 128 + nt * 16, 128);
            wmma::mma_sync(acc, af, bf2, acc);
        }
        #pragma unroll
        for (int k0 = 0; k0 < 16; ++k0) {
            FragA af; FragB bf2;
            wmma::load_matrix_sync(af, sScal + mt * 16 * VLD + k0 * 8, VLD);
            wmma::load_matrix_sync(bf2, g_m1 + (128 + k0 * 8) * 128 + nt * 16, 128);
            wmma::mma_sync(acc, af, bf2, acc);
        }
        wmma::store_matrix_sync(sH + mt * 16 * VLD + nt * 16, acc, VLD, wmma::mem_row_major);
    }
    __syncthreads();

    // silu + round
    for (int q = tid; q < TM * 128; q += NTHREADS) {
        int n = q >> 7, g = q & 127;
        float x = sH[n * VLD + g] + m1_b[g];
        float s = x / (1.0f + __expf(-x));
        sH[n * VLD + g] = ftf32(s);
    }
    __syncthreads();

    // ---------- Stage 4: G3 = h(32x128) @ m2(128x384) ----------
    // 24 col tiles x 2 m tiles; pass0: nt=w (all 16 warps), pass1: nt=w+16 (warps 0..7)
    float* sOut = sVv;   // [3][32][VLD]: a_vv, a_sv, a_ss
    #pragma unroll
    for (int pass = 0; pass < 2; ++pass) {
        int nt = w + pass * 16;
        if (nt < 24) {
            FragB bf[16];
            #pragma unroll
            for (int k0 = 0; k0 < 16; ++k0)
                wmma::load_matrix_sync(bf[k0], g_m2 + k0 * 8 * 384 + nt * 16, 384);
            int blk  = nt >> 3;
            int colc = (nt & 7) * 16;
            for (int mt = 0; mt < 2; ++mt) {
                FragC acc;
                wmma::fill_fragment(acc, 0.0f);
                #pragma unroll
                for (int k0 = 0; k0 < 16; ++k0) {
                    FragA af;
                    wmma::load_matrix_sync(af, sH + mt * 16 * VLD + k0 * 8, VLD);
                    wmma::mma_sync(acc, af, bf[k0], acc);
                }
                wmma::store_matrix_sync(sOut + blk * 32 * VLD + mt * 16 * VLD + colc,
                                        acc, VLD, wmma::mem_row_major);
            }
        }
    }
    __syncthreads();

    // ---------- Stage 5: epilogue (fp32 residual path, vectorized) ----------
    for (int q = tid; q < TM * 32; q += NTHREADS) {
        int n = q >> 5;
        int g = (q & 31) * 4;
        float4 avv = *reinterpret_cast<float4*>(sOut + 0 * 32 * VLD + n * VLD + g);
        float4 asv = *reinterpret_cast<float4*>(sOut + 1 * 32 * VLD + n * VLD + g);
        float4 ass = *reinterpret_cast<float4*>(sOut + 2 * 32 * VLD + n * VLD + g);
        float4 b0 = *reinterpret_cast<const float4*>(m2_b + g);
        float4 b1 = *reinterpret_cast<const float4*>(m2_b + 128 + g);
        float4 b2 = *reinterpret_cast<const float4*>(m2_b + 256 + g);
        avv.x += b0.x; avv.y += b0.y; avv.z += b0.z; avv.w += b0.w;
        asv.x += b1.x; asv.y += b1.y; asv.z += b1.z; asv.w += b1.w;
        ass.x += b2.x; ass.y += b2.y; ass.z += b2.z; ass.w += b2.w;
        float4 inn = *reinterpret_cast<float4*>(sInner + n * VLD + g);

        const float* nfr = node_feat + base + n * 512;
        float* outr = out + base + n * 512;

        float4 s = *reinterpret_cast<const float4*>(nfr + g);
        float4 os;
        os.x = s.x + asv.x * inn.x + ass.x;
        os.y = s.y + asv.y * inn.y + ass.y;
        os.z = s.z + asv.z * inn.z + ass.z;
        os.w = s.w + asv.w * inn.w + ass.w;
        *reinterpret_cast<float4*>(outr + g) = os;

        #pragma unroll
        for (int c = 0; c < 3; ++c) {
            float4 u = *reinterpret_cast<float4*>(sUv + (3 * n + c) * VLD + g);
            float4 v = *reinterpret_cast<const float4*>(nfr + 128 + c * 128 + g);
            float4 ov;
            ov.x = v.x + avv.x * u.x;
            ov.y = v.y + avv.y * u.y;
            ov.z = v.z + avv.z * u.z;
            ov.w = v.w + avv.w * u.w;
            *reinterpret_cast<float4*>(outr + 128 + c * 128 + g) = ov;
        }
    }
}

extern "C" void kernel_launch(void* const* d_in, const int* in_sizes, int n_in,
                              void* d_out, int out_size) {
    const float* node_feat = (const float*)d_in[0];
    const float* U_w  = (const float*)d_in[1];
    const float* U_b  = (const float*)d_in[2];
    const float* V_w  = (const float*)d_in[3];
    const float* V_b  = (const float*)d_in[4];
    const float* m1_w = (const float*)d_in[5];
    const float* m1_b = (const float*)d_in[6];
    const float* m2_w = (const float*)d_in[7];
    const float* m2_b = (const float*)d_in[8];
    float* out = (float*)d_out;

    int N = in_sizes[0] / (4 * FDIM);

    prep_kernel<<<(128 * 384 + 255) / 256, 256>>>(U_w, V_w, m1_w, m2_w);

    size_t smem_bytes = (size_t)(3 * 96 * VLD + 4 * 32 * VLD) * sizeof(float);
    cudaFuncSetAttribute(painn_kernel,
                         cudaFuncAttributeMaxDynamicSharedMemorySize,
                         (int)smem_bytes);
    painn_kernel<<<N / TM, NTHREADS, smem_bytes>>>(node_feat, U_b, V_b, m1_b, m2_b, out);
}

// round 4
// speedup vs baseline: 1.2700x; 1.0210x over previous
#include <cuda_runtime.h>
#include <mma.h>

using namespace nvcuda;

#define FDIM     128
#define TM       32          // nodes per CTA
#define VLD      132         // smem leading dim (floats), mult of 4
#define NTHREADS 512         // 16 warps

// Pre-converted (tf32-rounded) weights, filled by prep_kernel each launch.
__device__ float g_wcat[128 * 256];   // [k][0:128]=U_w, [k][128:256]=V_w
__device__ float g_m1[256 * 128];
__device__ float g_m2[128 * 384];

__device__ __forceinline__ float ftf32(float x) {
    float y;
    asm("cvt.rna.tf32.f32 %0, %1;" : "=f"(y) : "f"(x));
    return y;
}

__global__ void prep_kernel(const float* __restrict__ Uw,
                            const float* __restrict__ Vw,
                            const float* __restrict__ m1w,
                            const float* __restrict__ m2w) {
    int i = blockIdx.x * blockDim.x + threadIdx.x;
    if (i < 128 * 128) {
        int k = i >> 7, g = i & 127;
        g_wcat[k * 256 + g]       = ftf32(Uw[i]);
        g_wcat[k * 256 + 128 + g] = ftf32(Vw[i]);
    }
    if (i < 256 * 128) g_m1[i] = ftf32(m1w[i]);
    if (i < 128 * 384) g_m2[i] = ftf32(m2w[i]);
}

using FragA = wmma::fragment<wmma::matrix_a, 16, 16, 8, wmma::precision::tf32, wmma::row_major>;
using FragB = wmma::fragment<wmma::matrix_b, 16, 16, 8, wmma::precision::tf32, wmma::row_major>;
using FragC = wmma::fragment<wmma::accumulator, 16, 16, 8, float>;

__global__ __launch_bounds__(NTHREADS, 1)
void painn_kernel(const float* __restrict__ node_feat,
                  const float* __restrict__ U_b,
                  const float* __restrict__ V_b,
                  const float* __restrict__ m1_b,
                  const float* __restrict__ m2_b,
                  float* __restrict__ out) {
    extern __shared__ float smem[];
    float* sVec   = smem;                 // 96 x VLD : vec rows r=n*3+c (tf32-rounded)
    float* sUv    = sVec   + 96 * VLD;    // 96 x VLD
    float* sVv    = sUv    + 96 * VLD;    // 96 x VLD, reused later as sOut[3][32][VLD]
    float* sScal  = sVv    + 96 * VLD;    // 32 x VLD (tf32-rounded scalars)
    float* sVn    = sScal  + 32 * VLD;    // 32 x VLD
    float* sInner = sVn    + 32 * VLD;    // 32 x VLD (fp32)
    float* sH     = sInner + 32 * VLD;    // 32 x VLD

    const int tid = threadIdx.x;
    const int w   = tid >> 5;             // 0..15
    const int base = blockIdx.x * (TM * 4 * FDIM);
    const float* nf = node_feat + base;

    // ---------- Stage 0: stage node tile into smem (tf32-rounded) ----------
    for (int q = tid; q < TM * 128; q += NTHREADS) {
        int n   = q >> 7;
        int f0  = (q & 127) * 4;
        float4 v = *reinterpret_cast<const float4*>(nf + n * 512 + f0);
        float r0 = ftf32(v.x), r1 = ftf32(v.y), r2 = ftf32(v.z), r3 = ftf32(v.w);
        float* dst;
        if (f0 < 128) {
            dst = sScal + n * VLD + f0;
        } else {
            int c = (f0 - 128) >> 7;
            int f = (f0 - 128) & 127;
            dst = sVec + (n * 3 + c) * VLD + f;
        }
        dst[0] = r0; dst[1] = r1; dst[2] = r2; dst[3] = r3;
    }
    __syncthreads();

    // ---------- Stage 1: G1 = vec(96x128) @ [U|V](128x256) ----------
    // One 16-col tile per warp; 3 m-tiles interleaved (independent acc chains).
    {
        const int nt = w;
        FragB bf[16];
        const float* bbase = g_wcat + nt * 16;
        #pragma unroll
        for (int k0 = 0; k0 < 16; ++k0)
            wmma::load_matrix_sync(bf[k0], bbase + k0 * 8 * 256, 256);
        float* dcol = (nt < 8 ? sUv + nt * 16 : sVv + (nt - 8) * 16);
        #pragma unroll
        for (int mp = 0; mp < 2; ++mp) {           // 2 passes x 3 tiles
            const int mt = mp * 3;
            FragC acc0, acc1, acc2;
            wmma::fill_fragment(acc0, 0.0f);
            wmma::fill_fragment(acc1, 0.0f);
            wmma::fill_fragment(acc2, 0.0f);
            #pragma unroll
            for (int k0 = 0; k0 < 16; ++k0) {
                FragA a0, a1, a2;
                wmma::load_matrix_sync(a0, sVec + (mt + 0) * 16 * VLD + k0 * 8, VLD);
                wmma::load_matrix_sync(a1, sVec + (mt + 1) * 16 * VLD + k0 * 8, VLD);
                wmma::load_matrix_sync(a2, sVec + (mt + 2) * 16 * VLD + k0 * 8, VLD);
                wmma::mma_sync(acc0, a0, bf[k0], acc0);
                wmma::mma_sync(acc1, a1, bf[k0], acc1);
                wmma::mma_sync(acc2, a2, bf[k0], acc2);
            }
            wmma::store_matrix_sync(dcol + (mt + 0) * 16 * VLD, acc0, VLD, wmma::mem_row_major);
            wmma::store_matrix_sync(dcol + (mt + 1) * 16 * VLD, acc1, VLD, wmma::mem_row_major);
            wmma::store_matrix_sync(dcol + (mt + 2) * 16 * VLD, acc2, VLD, wmma::mem_row_major);
        }
    }
    __syncthreads();

    // ---------- Stage 2: bias, Vv_norm, inner product ----------
    for (int q = tid; q < TM * 128; q += NTHREADS) {
        int n = q >> 7, g = q & 127;
        float ub = U_b[g], vb = V_b[g];
        int r = 3 * n;
        float u0 = sUv[(r + 0) * VLD + g] + ub;
        float u1 = sUv[(r + 1) * VLD + g] + ub;
        float u2 = sUv[(r + 2) * VLD + g] + ub;
        float v0 = sVv[(r + 0) * VLD + g] + vb;
        float v1 = sVv[(r + 1) * VLD + g] + vb;
        float v2 = sVv[(r + 2) * VLD + g] + vb;
        sUv[(r + 0) * VLD + g] = u0;   // keep biased Uv for epilogue
        sUv[(r + 1) * VLD + g] = u1;
        sUv[(r + 2) * VLD + g] = u2;
        sVn[n * VLD + g]    = ftf32(sqrtf(v0 * v0 + v1 * v1 + v2 * v2));
        sInner[n * VLD + g] = u0 * v0 + u1 * v1 + u2 * v2;
    }
    __syncthreads();     // Vv dead -> its space becomes sOut

    // ---------- Stage 3: G2 = [Vn | scal](32x256) @ m1(256x128) ----------
    // 16 tasks: mt = w&1, nt = w>>1.  4 independent acc chains of 8 k-steps.
    {
        const int mt = w & 1;
        const int nt = w >> 1;
        FragC acc0, acc1, acc2, acc3;
        wmma::fill_fragment(acc0, 0.0f);
        wmma::fill_fragment(acc1, 0.0f);
        wmma::fill_fragment(acc2, 0.0f);
        wmma::fill_fragment(acc3, 0.0f);
        #pragma unroll
        for (int k0 = 0; k0 < 8; ++k0) {
            FragA a0, a1, a2, a3;
            FragB b0, b1, b2, b3;
            wmma::load_matrix_sync(a0, sVn   + mt * 16 * VLD + k0 * 8, VLD);
            wmma::load_matrix_sync(a1, sVn   + mt * 16 * VLD + (k0 + 8) * 8, VLD);
            wmma::load_matrix_sync(a2, sScal + mt * 16 * VLD + k0 * 8, VLD);
            wmma::load_matrix_sync(a3, sScal + mt * 16 * VLD + (k0 + 8) * 8, VLD);
            wmma::load_matrix_sync(b0, g_m1 + (k0 * 8)         * 128 + nt * 16, 128);
            wmma::load_matrix_sync(b1, g_m1 + ((k0 + 8) * 8)   * 128 + nt * 16, 128);
            wmma::load_matrix_sync(b2, g_m1 + (128 + k0 * 8)   * 128 + nt * 16, 128);
            wmma::load_matrix_sync(b3, g_m1 + (192 + k0 * 8)   * 128 + nt * 16, 128);
            wmma::mma_sync(acc0, a0, b0, acc0);
            wmma::mma_sync(acc1, a1, b1, acc1);
            wmma::mma_sync(acc2, a2, b2, acc2);
            wmma::mma_sync(acc3, a3, b3, acc3);
        }
        #pragma unroll
        for (int i = 0; i < acc0.num_elements; ++i)
            acc0.x[i] += acc1.x[i] + acc2.x[i] + acc3.x[i];
        wmma::store_matrix_sync(sH + mt * 16 * VLD + nt * 16, acc0, VLD, wmma::mem_row_major);
    }
    __syncthreads();

    // silu + round
    for (int q = tid; q < TM * 128; q += NTHREADS) {
        int n = q >> 7, g = q & 127;
        float x = sH[n * VLD + g] + m1_b[g];
        float s = x / (1.0f + __expf(-x));
        sH[n * VLD + g] = ftf32(s);
    }
    __syncthreads();

    // ---------- Stage 4: G3 = h(32x128) @ m2(128x384) ----------
    // 24 col tiles; pass0: nt=w, pass1: nt=w+16 (warps 0..7). Both m-tiles interleaved.
    float* sOut = sVv;   // [3][32][VLD]: a_vv, a_sv, a_ss
    #pragma unroll
    for (int pass = 0; pass < 2; ++pass) {
        int nt = w + pass * 16;
        if (nt < 24) {
            FragB bf[16];
            #pragma unroll
            for (int k0 = 0; k0 < 16; ++k0)
                wmma::load_matrix_sync(bf[k0], g_m2 + k0 * 8 * 384 + nt * 16, 384);
            int blk  = nt >> 3;
            int colc = (nt & 7) * 16;
            FragC acc0, acc1;
            wmma::fill_fragment(acc0, 0.0f);
            wmma::fill_fragment(acc1, 0.0f);
            #pragma unroll
            for (int k0 = 0; k0 < 16; ++k0) {
                FragA a0, a1;
                wmma::load_matrix_sync(a0, sH + 0 * 16 * VLD + k0 * 8, VLD);
                wmma::load_matrix_sync(a1, sH + 1 * 16 * VLD + k0 * 8, VLD);
                wmma::mma_sync(acc0, a0, bf[k0], acc0);
                wmma::mma_sync(acc1, a1, bf[k0], acc1);
            }
            wmma::store_matrix_sync(sOut + blk * 32 * VLD + 0 * 16 * VLD + colc,
                                    acc0, VLD, wmma::mem_row_major);
            wmma::store_matrix_sync(sOut + blk * 32 * VLD + 1 * 16 * VLD + colc,
                                    acc1, VLD, wmma::mem_row_major);
        }
    }
    __syncthreads();

    // ---------- Stage 5: epilogue (fp32 residual path, vectorized) ----------
    for (int q = tid; q < TM * 32; q += NTHREADS) {
        int n = q >> 5;
        int g = (q & 31) * 4;
        float4 avv = *reinterpret_cast<float4*>(sOut + 0 * 32 * VLD + n * VLD + g);
        float4 asv = *reinterpret_cast<float4*>(sOut + 1 * 32 * VLD + n * VLD + g);
        float4 ass = *reinterpret_cast<float4*>(sOut + 2 * 32 * VLD + n * VLD + g);
        float4 b0 = *reinterpret_cast<const float4*>(m2_b + g);
        float4 b1 = *reinterpret_cast<const float4*>(m2_b + 128 + g);
        float4 b2 = *reinterpret_cast<const float4*>(m2_b + 256 + g);
        avv.x += b0.x; avv.y += b0.y; avv.z += b0.z; avv.w += b0.w;
        asv.x += b1.x; asv.y += b1.y; asv.z += b1.z; asv.w += b1.w;
        ass.x += b2.x; ass.y += b2.y; ass.z += b2.z; ass.w += b2.w;
        float4 inn = *reinterpret_cast<float4*>(sInner + n * VLD + g);

        const float* nfr = node_feat + base + n * 512;
        float* outr = out + base + n * 512;

        float4 s = *reinterpret_cast<const float4*>(nfr + g);
        float4 os;
        os.x = s.x + asv.x * inn.x + ass.x;
        os.y = s.y + asv.y * inn.y + ass.y;
        os.z = s.z + asv.z * inn.z + ass.z;
        os.w = s.w + asv.w * inn.w + ass.w;
        *reinterpret_cast<float4*>(outr + g) = os;

        #pragma unroll
        for (int c = 0; c < 3; ++c) {
            float4 u = *reinterpret_cast<float4*>(sUv + (3 * n + c) * VLD + g);
            float4 v = *reinterpret_cast<const float4*>(nfr + 128 + c * 128 + g);
            float4 ov;
            ov.x = v.x + avv.x * u.x;
            ov.y = v.y + avv.y * u.y;
            ov.z = v.z + avv.z * u.z;
            ov.w = v.w + avv.w * u.w;
            *reinterpret_cast<float4*>(outr + 128 + c * 128 + g) = ov;
        }
    }
}

extern "C" void kernel_launch(void* const* d_in, const int* in_sizes, int n_in,
                              void* d_out, int out_size) {
    const float* node_feat = (const float*)d_in[0];
    const float* U_w  = (const float*)d_in[1];
    const float* U_b  = (const float*)d_in[2];
    const float* V_w  = (const float*)d_in[3];
    const float* V_b  = (const float*)d_in[4];
    const float* m1_w = (const float*)d_in[5];
    const float* m1_b = (const float*)d_in[6];
    const float* m2_w = (const float*)d_in[7];
    const float* m2_b = (const float*)d_in[8];
    float* out = (float*)d_out;

    int N = in_sizes[0] / (4 * FDIM);

    prep_kernel<<<(128 * 384 + 255) / 256, 256>>>(U_w, V_w, m1_w, m2_w);

    size_t smem_bytes = (size_t)(3 * 96 * VLD + 4 * 32 * VLD) * sizeof(float);
    cudaFuncSetAttribute(painn_kernel,
                         cudaFuncAttributeMaxDynamicSharedMemorySize,
                         (int)smem_bytes);
    painn_kernel<<<N / TM, NTHREADS, smem_bytes>>>(node_feat, U_b, V_b, m1_b, m2_b, out);
}